// round 12
// baseline (speedup 1.0000x reference)
#include <cuda_runtime.h>
#include <cstdint>

// ---------------------------------------------------------------------------
// Problem constants
// ---------------------------------------------------------------------------
static constexpr int B_WIN  = 2048;
static constexpr int NTOK   = 49;
static constexpr int CDIM   = 384;
static constexpr int NHEAD  = 12;
static constexpr int DHEAD  = 32;
static constexpr int NW     = 64;
static constexpr int MROWS  = B_WIN * NTOK;   // 100352
static constexpr int QKVN   = 3 * CDIM;       // 1152

// Scratch (no cudaMalloc allowed)
__device__ float g_qkv[(size_t)MROWS * QKVN];
__device__ float g_att[(size_t)MROWS * CDIM];

// ---------------------------------------------------------------------------
// Helpers
// ---------------------------------------------------------------------------
__device__ __forceinline__ uint32_t f2tf32(float x) {
    uint32_t r;
    asm("cvt.rna.tf32.f32 %0, %1;\n" : "=r"(r) : "f"(x));
    return r;
}
__device__ __forceinline__ float roundtf(float x) { return __uint_as_float(f2tf32(x)); }
__device__ __forceinline__ uint32_t fbits(float x) { return __float_as_uint(x); }
__device__ __forceinline__ void mma_tf32(float* c, const uint32_t* a, const uint32_t* b) {
    asm volatile(
        "mma.sync.aligned.m16n8k8.row.col.f32.tf32.tf32.f32 "
        "{%0,%1,%2,%3}, {%4,%5,%6,%7}, {%8,%9}, {%0,%1,%2,%3};\n"
        : "+f"(c[0]), "+f"(c[1]), "+f"(c[2]), "+f"(c[3])
        : "r"(a[0]), "r"(a[1]), "r"(a[2]), "r"(a[3]), "r"(b[0]), "r"(b[1]));
}

// ---------------------------------------------------------------------------
// TF32 GEMM with crosswise smem layout:  C[M,N] = A[M,K] @ B[N,K]^T + bias[N]
// 128x128x16 tiles, 8 warps (64x32 warp tile), 256 threads.
// Smem row (16 k-floats) stored permuted: word p holds k with
//   p = 4*(k&3) + (k>>2)   =>   LDS.128 @ 4*tig = {k=tig, tig+4, tig+8, tig+12}
// Loader: LDG (16B-coalesced groups) + cvt.rna.tf32 + STS.128, reg prefetch,
// double-buffered smem. Fragments come from 12 LDS.128 per warp per kt.
// ---------------------------------------------------------------------------
#define GBM 128
#define GBN 128
#define GBK 16
#define TSW 16                       // smem row stride in words (64B)
#define TILE_FLOATS (GBM * TSW)      // 2048 floats per matrix tile

__global__ __launch_bounds__(256, 2)
void gemm_tf32_cw(const float* __restrict__ A,
                  const float* __restrict__ B,
                  const float* __restrict__ bias,
                  float* __restrict__ C,
                  int M, int N, int K)
{
    __shared__ float sm[2][2 * TILE_FLOATS];   // [stage][A | B]  (32 KB total)

    const int tid  = threadIdx.x;
    const int wid  = tid >> 5;
    const int lane = tid & 31;
    const int g    = lane >> 2;
    const int tig  = lane & 3;

    const int m0 = blockIdx.y * GBM;
    const int n0 = blockIdx.x * GBN;
    const int warp_m = wid >> 2;     // 0..1 -> 64-row slab
    const int warp_n = wid & 3;      // 0..3 -> 32-col slab
    const int KT = K / GBK;

    float acc[4][4][4];
#pragma unroll
    for (int mt = 0; mt < 4; mt++)
#pragma unroll
        for (int nt = 0; nt < 4; nt++)
#pragma unroll
            for (int r = 0; r < 4; r++) acc[mt][nt][r] = 0.0f;

    // Loader decode: 4 units/thread; id = u*256+tid in [0,1024)
    //   mat = id>>9 (0=A,1=B), row = (id>>2)&127, chunk = id&3
    // Unit's STS.128 at word row*TSW + chunk*4 holds elements k = chunk + 4s.
    float pre[4][4];     // prefetch registers [unit][s]

    auto ldg_tile = [&](int kt) {
#pragma unroll
        for (int u = 0; u < 4; u++) {
            int id   = u * 256 + tid;
            int mat  = id >> 9;
            int row  = (id >> 2) & 127;
            int ch   = id & 3;
            const float* p = (mat ? B + (size_t)(n0 + row) * K
                                  : A + (size_t)(m0 + row) * K) + kt * GBK + ch;
#pragma unroll
            for (int s = 0; s < 4; s++) pre[u][s] = p[4 * s];
        }
    };
    auto sts_tile = [&](int st) {
#pragma unroll
        for (int u = 0; u < 4; u++) {
            int id   = u * 256 + tid;
            int mat  = id >> 9;
            int row  = (id >> 2) & 127;
            int ch   = id & 3;
            uint4 v;
            v.x = f2tf32(pre[u][0]);
            v.y = f2tf32(pre[u][1]);
            v.z = f2tf32(pre[u][2]);
            v.w = f2tf32(pre[u][3]);
            *(uint4*)&sm[st][mat * TILE_FLOATS + row * TSW + ch * 4] = v;
        }
    };

    ldg_tile(0);
    sts_tile(0);
    __syncthreads();

    for (int kt = 0; kt < KT; kt++) {
        if (kt + 1 < KT) ldg_tile(kt + 1);      // issue early, consume late

        const float* sA = &sm[kt & 1][0];
        const float* sB = &sm[kt & 1][TILE_FLOATS];

        float4 Bv[4];
#pragma unroll
        for (int nt = 0; nt < 4; nt++) {
            int n = warp_n * 32 + nt * 8 + g;
            Bv[nt] = *(const float4*)&sB[n * TSW + tig * 4];
        }
#pragma unroll
        for (int mt = 0; mt < 4; mt++) {
            int r = warp_m * 64 + mt * 16 + g;
            float4 a0 = *(const float4*)&sA[r * TSW + tig * 4];
            float4 a1 = *(const float4*)&sA[(r + 8) * TSW + tig * 4];
            uint32_t af0[4] = { fbits(a0.x), fbits(a1.x), fbits(a0.y), fbits(a1.y) };
            uint32_t af1[4] = { fbits(a0.z), fbits(a1.z), fbits(a0.w), fbits(a1.w) };
#pragma unroll
            for (int nt = 0; nt < 4; nt++) {
                uint32_t b0[2] = { fbits(Bv[nt].x), fbits(Bv[nt].y) };
                mma_tf32(acc[mt][nt], af0, b0);
            }
#pragma unroll
            for (int nt = 0; nt < 4; nt++) {
                uint32_t b1[2] = { fbits(Bv[nt].z), fbits(Bv[nt].w) };
                mma_tf32(acc[mt][nt], af1, b1);
            }
        }

        if (kt + 1 < KT) sts_tile((kt + 1) & 1);   // write other buffer
        __syncthreads();
    }

    // ---- epilogue: bias + store ----
#pragma unroll
    for (int mt = 0; mt < 4; mt++) {
        int r0 = m0 + warp_m * 64 + mt * 16 + g;
#pragma unroll
        for (int nt = 0; nt < 4; nt++) {
            int c = n0 + warp_n * 32 + nt * 8 + tig * 2;
            float b0 = bias[c];
            float b1 = bias[c + 1];
            float2 v0 = make_float2(acc[mt][nt][0] + b0, acc[mt][nt][1] + b1);
            float2 v1 = make_float2(acc[mt][nt][2] + b0, acc[mt][nt][3] + b1);
            *(float2*)(C + (size_t)r0 * N + c)       = v0;
            *(float2*)(C + (size_t)(r0 + 8) * N + c) = v1;
        }
    }
}

// ---------------------------------------------------------------------------
// Tensor-core window attention (R10-measured): one block (128 thr) per (b, h).
// ---------------------------------------------------------------------------
#define QS 36
#define PS 68
#define MSK 52

__global__ __launch_bounds__(128, 6)
void attn_mma(const float* __restrict__ qkv,
              const float* __restrict__ mask,
              const float* __restrict__ bias_table,
              float* __restrict__ out)
{
    const int b   = blockIdx.x;
    const int h   = blockIdx.y;
    const int tid = threadIdx.x;
    const int wid = tid >> 5;
    const int lane = tid & 31;
    const int g   = lane >> 2;
    const int tig = lane & 3;
    const float scale = 0.17677669529663689f;

    __shared__ float sQK[2 * 64 * QS];     // sQ | sK ; reused as sP[64][PS]
    __shared__ float sV[64][QS];
    __shared__ float sBias[169];
    __shared__ float sMask[NTOK * MSK];

    float* sQ = sQK;
    float* sK = sQK + 64 * QS;
    float* sP = sQK;

    for (int idx = tid; idx < 64 * DHEAD; idx += 128) {
        int n = idx >> 5;
        int d = idx & 31;
        float q = 0.f, k = 0.f, v = 0.f;
        if (n < NTOK) {
            const float* base = qkv + (size_t)(b * NTOK + n) * QKVN + h * DHEAD + d;
            q = base[0] * scale;
            k = base[CDIM];
            v = base[2 * CDIM];
        }
        sQ[n * QS + d] = roundtf(q);
        sK[n * QS + d] = roundtf(k);
        sV[n][d] = roundtf(v);
    }
    for (int i = tid; i < 169; i += 128) sBias[i] = bias_table[i * NHEAD + h];
    {
        const float* mrow = mask + (size_t)(b & (NW - 1)) * NTOK * NTOK;
        for (int i = tid; i < NTOK * NTOK; i += 128) {
            int r = i / NTOK;
            int c = i - r * NTOK;
            sMask[r * MSK + c] = mrow[i];
        }
    }
    __syncthreads();

    const int r0 = wid * 16;

    float sacc[8][4];
#pragma unroll
    for (int nt = 0; nt < 8; nt++)
#pragma unroll
        for (int c = 0; c < 4; c++) sacc[nt][c] = 0.f;

#pragma unroll
    for (int ks = 0; ks < 4; ks++) {
        const int k0 = ks * 8;
        uint32_t a[4];
        a[0] = fbits(sQ[(r0 + g    ) * QS + k0 + tig    ]);
        a[1] = fbits(sQ[(r0 + g + 8) * QS + k0 + tig    ]);
        a[2] = fbits(sQ[(r0 + g    ) * QS + k0 + tig + 4]);
        a[3] = fbits(sQ[(r0 + g + 8) * QS + k0 + tig + 4]);
#pragma unroll
        for (int nt = 0; nt < 8; nt++) {
            uint32_t bb[2];
            bb[0] = fbits(sK[(nt * 8 + g) * QS + k0 + tig    ]);
            bb[1] = fbits(sK[(nt * 8 + g) * QS + k0 + tig + 4]);
            mma_tf32(sacc[nt], a, bb);
        }
    }
    __syncthreads();   // all warps done reading sQ/sK before sP (alias) writes

    const int iA = r0 + g;
    const int iB = r0 + g + 8;
    const int yA = iA / 7, xA = iA - yA * 7;
    const int yB = iB / 7, xB = iB - yB * 7;
#pragma unroll
    for (int nt = 0; nt < 8; nt++) {
        const int j0 = nt * 8 + tig * 2;
#pragma unroll
        for (int u = 0; u < 2; u++) {
            int j = j0 + u;
            if (j < NTOK) {
                int yj = j / 7, xj = j - yj * 7;
                if (iA < NTOK) {
                    int rel = (yA - yj + 6) * 13 + (xA - xj + 6);
                    sacc[nt][u] += sBias[rel] + sMask[iA * MSK + j];
                } else sacc[nt][u] = -1e30f;
                if (iB < NTOK) {
                    int rel = (yB - yj + 6) * 13 + (xB - xj + 6);
                    sacc[nt][u + 2] += sBias[rel] + sMask[iB * MSK + j];
                } else sacc[nt][u + 2] = -1e30f;
            } else {
                sacc[nt][u]     = -1e30f;
                sacc[nt][u + 2] = -1e30f;
            }
        }
    }

    float mA = -1e30f, mB = -1e30f;
#pragma unroll
    for (int nt = 0; nt < 8; nt++) {
        mA = fmaxf(mA, fmaxf(sacc[nt][0], sacc[nt][1]));
        mB = fmaxf(mB, fmaxf(sacc[nt][2], sacc[nt][3]));
    }
    mA = fmaxf(mA, __shfl_xor_sync(0xffffffff, mA, 1));
    mA = fmaxf(mA, __shfl_xor_sync(0xffffffff, mA, 2));
    mB = fmaxf(mB, __shfl_xor_sync(0xffffffff, mB, 1));
    mB = fmaxf(mB, __shfl_xor_sync(0xffffffff, mB, 2));

    float sumA = 0.f, sumB = 0.f;
#pragma unroll
    for (int nt = 0; nt < 8; nt++) {
        sacc[nt][0] = __expf(sacc[nt][0] - mA);
        sacc[nt][1] = __expf(sacc[nt][1] - mA);
        sacc[nt][2] = __expf(sacc[nt][2] - mB);
        sacc[nt][3] = __expf(sacc[nt][3] - mB);
        sumA += sacc[nt][0] + sacc[nt][1];
        sumB += sacc[nt][2] + sacc[nt][3];
    }
    sumA += __shfl_xor_sync(0xffffffff, sumA, 1);
    sumA += __shfl_xor_sync(0xffffffff, sumA, 2);
    sumB += __shfl_xor_sync(0xffffffff, sumB, 1);
    sumB += __shfl_xor_sync(0xffffffff, sumB, 2);
    const float invA = 1.0f / sumA;
    const float invB = 1.0f / sumB;

#pragma unroll
    for (int nt = 0; nt < 8; nt++) {
        const int j0 = nt * 8 + tig * 2;
        *(float2*)&sP[iA * PS + j0] =
            make_float2(roundtf(sacc[nt][0] * invA), roundtf(sacc[nt][1] * invA));
        *(float2*)&sP[iB * PS + j0] =
            make_float2(roundtf(sacc[nt][2] * invB), roundtf(sacc[nt][3] * invB));
    }
    __syncwarp();

    float oacc[4][4];
#pragma unroll
    for (int nt = 0; nt < 4; nt++)
#pragma unroll
        for (int c = 0; c < 4; c++) oacc[nt][c] = 0.f;

#pragma unroll
    for (int ks = 0; ks < 8; ks++) {
        const int k0 = ks * 8;
        uint32_t a[4];
        a[0] = fbits(sP[(r0 + g    ) * PS + k0 + tig    ]);
        a[1] = fbits(sP[(r0 + g + 8) * PS + k0 + tig    ]);
        a[2] = fbits(sP[(r0 + g    ) * PS + k0 + tig + 4]);
        a[3] = fbits(sP[(r0 + g + 8) * PS + k0 + tig + 4]);
#pragma unroll
        for (int nt = 0; nt < 4; nt++) {
            uint32_t bb[2];
            bb[0] = fbits(sV[k0 + tig    ][nt * 8 + g]);
            bb[1] = fbits(sV[k0 + tig + 4][nt * 8 + g]);
            mma_tf32(oacc[nt], a, bb);
        }
    }

#pragma unroll
    for (int nt = 0; nt < 4; nt++) {
        const int d0 = nt * 8 + tig * 2;
        if (iA < NTOK)
            *(float2*)(out + (size_t)(b * NTOK + iA) * CDIM + h * DHEAD + d0) =
                make_float2(oacc[nt][0], oacc[nt][1]);
        if (iB < NTOK)
            *(float2*)(out + (size_t)(b * NTOK + iB) * CDIM + h * DHEAD + d0) =
                make_float2(oacc[nt][2], oacc[nt][3]);
    }
}

// ---------------------------------------------------------------------------
// Launch
// ---------------------------------------------------------------------------
extern "C" void kernel_launch(void* const* d_in, const int* in_sizes, int n_in,
                              void* d_out, int out_size)
{
    const float* x          = (const float*)d_in[0];
    const float* mask       = (const float*)d_in[1];
    const float* qkv_w      = (const float*)d_in[2];
    const float* qkv_b      = (const float*)d_in[3];
    const float* proj_w     = (const float*)d_in[4];
    const float* proj_b     = (const float*)d_in[5];
    const float* bias_table = (const float*)d_in[6];
    float* out = (float*)d_out;

    float* qkv;  cudaGetSymbolAddress((void**)&qkv, g_qkv);
    float* att;  cudaGetSymbolAddress((void**)&att, g_att);

    // 1) QKV projection
    {
        dim3 grid(QKVN / GBN, MROWS / GBM);   // (9, 784)
        gemm_tf32_cw<<<grid, 256>>>(x, qkv_w, qkv_b, qkv, MROWS, QKVN, CDIM);
    }

    // 2) Tensor-core windowed attention
    {
        dim3 grid(B_WIN, NHEAD);
        attn_mma<<<grid, 128>>>(qkv, mask, bias_table, att);
    }

    // 3) Output projection
    {
        dim3 grid(CDIM / GBN, MROWS / GBM);   // (3, 784)
        gemm_tf32_cw<<<grid, 256>>>(att, proj_w, proj_b, out, MROWS, CDIM, CDIM);
    }
}

// round 13
// speedup vs baseline: 1.8315x; 1.8315x over previous
#include <cuda_runtime.h>
#include <cstdint>

// ---------------------------------------------------------------------------
// Problem constants
// ---------------------------------------------------------------------------
static constexpr int B_WIN  = 2048;
static constexpr int NTOK   = 49;
static constexpr int CDIM   = 384;
static constexpr int NHEAD  = 12;
static constexpr int DHEAD  = 32;
static constexpr int NW     = 64;
static constexpr int MROWS  = B_WIN * NTOK;   // 100352
static constexpr int QKVN   = 3 * CDIM;       // 1152

// Scratch (no cudaMalloc allowed)
__device__ float g_qkv[(size_t)MROWS * QKVN];
__device__ float g_att[(size_t)MROWS * CDIM];

// ---------------------------------------------------------------------------
// Helpers
// ---------------------------------------------------------------------------
__device__ __forceinline__ uint32_t f2tf32(float x) {
    uint32_t r;
    asm("cvt.rna.tf32.f32 %0, %1;\n" : "=r"(r) : "f"(x));
    return r;
}
__device__ __forceinline__ float roundtf(float x) { return __uint_as_float(f2tf32(x)); }
__device__ __forceinline__ uint32_t fbits(float x) { return __float_as_uint(x); }
__device__ __forceinline__ void mma_tf32(float* c, const uint32_t* a, const uint32_t* b) {
    asm volatile(
        "mma.sync.aligned.m16n8k8.row.col.f32.tf32.tf32.f32 "
        "{%0,%1,%2,%3}, {%4,%5,%6,%7}, {%8,%9}, {%0,%1,%2,%3};\n"
        : "+f"(c[0]), "+f"(c[1]), "+f"(c[2]), "+f"(c[3])
        : "r"(a[0]), "r"(a[1]), "r"(a[2]), "r"(a[3]), "r"(b[0]), "r"(b[1]));
}

// ---------------------------------------------------------------------------
// TF32 GEMM, crosswise smem + rotation:  C[M,N] = A[M,K] @ B[N,K]^T + bias[N]
// Element (row, k) of a 128x16 tile lives at word:
//   row*16 + ((4*(k&3) + (k>>2) + 4*((row>>1)&3)) & 15)
// => consumer fragment {k = tig, tig+4, tig+8, tig+12} is ONE LDS.128 at
//    chunk (tig + (row>>1)) & 3 (conflict-free per quarter-warp);
// => producer: LDG.128 (coalesced) + 4 conflict-free STS.32 per 16B chunk.
// ---------------------------------------------------------------------------
#define GBM 128
#define GBN 128
#define GBK 16
#define TILE_W (GBM * GBK)           // 2048 words per matrix tile

__global__ __launch_bounds__(256, 2)
void gemm_tf32_cw(const float* __restrict__ A,
                  const float* __restrict__ B,
                  const float* __restrict__ bias,
                  float* __restrict__ C,
                  int M, int N, int K)
{
    __shared__ float sm[2][2 * TILE_W];      // [stage][A | B]  (32 KB)

    const int tid  = threadIdx.x;
    const int wid  = tid >> 5;
    const int lane = tid & 31;
    const int g    = lane >> 2;
    const int tig  = lane & 3;

    const int m0 = blockIdx.y * GBM;
    const int n0 = blockIdx.x * GBN;
    const int warp_m = wid >> 2;             // 0..1 -> 64-row slab
    const int warp_n = wid & 3;              // 0..3 -> 32-col slab
    const int KT = K / GBK;

    float acc[4][4][4];
#pragma unroll
    for (int mt = 0; mt < 4; mt++)
#pragma unroll
        for (int nt = 0; nt < 4; nt++)
#pragma unroll
            for (int r = 0; r < 4; r++) acc[mt][nt][r] = 0.0f;

    // ---- producer decode (4 units/thread; unit u handles chunk id u*256+tid)
    //   mat = id>>9, row = (id>>2)&127, c = id&3
    float4 pre[4];
    const float* gptr[4];
    int prow[4], pc[4], pmat[4];
#pragma unroll
    for (int u = 0; u < 4; u++) {
        int id  = u * 256 + tid;
        pmat[u] = id >> 9;
        prow[u] = (id >> 2) & 127;
        pc[u]   = id & 3;
        gptr[u] = (pmat[u] ? B + (size_t)(n0 + prow[u]) * K
                           : A + (size_t)(m0 + prow[u]) * K) + pc[u] * 4;
    }

    auto ldg_tile = [&](int kt) {
#pragma unroll
        for (int u = 0; u < 4; u++)
            pre[u] = *(const float4*)(gptr[u] + kt * GBK);
    };
    auto sts_tile = [&](int st) {
#pragma unroll
        for (int u = 0; u < 4; u++) {
            const int r2 = (prow[u] >> 1) & 3;
            float* base = &sm[st][pmat[u] * TILE_W + prow[u] * 16 + pc[u]];
            base[4 * (( r2     ) & 3)] = __uint_as_float(f2tf32(pre[u].x));
            base[4 * ((1 + r2  ) & 3)] = __uint_as_float(f2tf32(pre[u].y));
            base[4 * ((2 + r2  ) & 3)] = __uint_as_float(f2tf32(pre[u].z));
            base[4 * ((3 + r2  ) & 3)] = __uint_as_float(f2tf32(pre[u].w));
        }
    };

    // ---- consumer fragment offsets (kt-invariant) ----
    int aoff[4], boff[4];
#pragma unroll
    for (int mt = 0; mt < 4; mt++) {
        int r = warp_m * 64 + mt * 16 + g;
        aoff[mt] = r * 16 + 4 * ((tig + ((r >> 1) & 3)) & 3);
    }
#pragma unroll
    for (int nt = 0; nt < 4; nt++) {
        int n = warp_n * 32 + nt * 8 + g;
        boff[nt] = n * 16 + 4 * ((tig + ((n >> 1) & 3)) & 3);
    }

    ldg_tile(0);
    sts_tile(0);
    __syncthreads();

    for (int kt = 0; kt < KT; kt++) {
        if (kt + 1 < KT) ldg_tile(kt + 1);   // issue early, consume late

        const float* sA = &sm[kt & 1][0];
        const float* sB = &sm[kt & 1][TILE_W];

        // loaded float4 = k components {tig, tig+4, tig+8, tig+12}
        float4 Bv[4];
#pragma unroll
        for (int nt = 0; nt < 4; nt++)
            Bv[nt] = *(const float4*)&sB[boff[nt]];

#pragma unroll
        for (int mt = 0; mt < 4; mt++) {
            float4 a0 = *(const float4*)&sA[aoff[mt]];        // row r
            float4 a1 = *(const float4*)&sA[aoff[mt] + 128];  // row r+8 (same chunk)
            uint32_t af0[4] = { fbits(a0.x), fbits(a1.x), fbits(a0.y), fbits(a1.y) };
            uint32_t af1[4] = { fbits(a0.z), fbits(a1.z), fbits(a0.w), fbits(a1.w) };
#pragma unroll
            for (int nt = 0; nt < 4; nt++) {
                uint32_t b0[2] = { fbits(Bv[nt].x), fbits(Bv[nt].y) };
                mma_tf32(acc[mt][nt], af0, b0);
            }
#pragma unroll
            for (int nt = 0; nt < 4; nt++) {
                uint32_t b1[2] = { fbits(Bv[nt].z), fbits(Bv[nt].w) };
                mma_tf32(acc[mt][nt], af1, b1);
            }
        }

        if (kt + 1 < KT) sts_tile((kt + 1) & 1);
        __syncthreads();
    }

    // ---- epilogue: bias + store ----
#pragma unroll
    for (int mt = 0; mt < 4; mt++) {
        int r0 = m0 + warp_m * 64 + mt * 16 + g;
#pragma unroll
        for (int nt = 0; nt < 4; nt++) {
            int c = n0 + warp_n * 32 + nt * 8 + tig * 2;
            float b0 = bias[c];
            float b1 = bias[c + 1];
            float2 v0 = make_float2(acc[mt][nt][0] + b0, acc[mt][nt][1] + b1);
            float2 v1 = make_float2(acc[mt][nt][2] + b0, acc[mt][nt][3] + b1);
            *(float2*)(C + (size_t)r0 * N + c)       = v0;
            *(float2*)(C + (size_t)(r0 + 8) * N + c) = v1;
        }
    }
}

// ---------------------------------------------------------------------------
// Tensor-core window attention (R10-measured): one block (128 thr) per (b, h).
// ---------------------------------------------------------------------------
#define QS 36
#define PS 68
#define MSK 52

__global__ __launch_bounds__(128, 6)
void attn_mma(const float* __restrict__ qkv,
              const float* __restrict__ mask,
              const float* __restrict__ bias_table,
              float* __restrict__ out)
{
    const int b   = blockIdx.x;
    const int h   = blockIdx.y;
    const int tid = threadIdx.x;
    const int wid = tid >> 5;
    const int lane = tid & 31;
    const int g   = lane >> 2;
    const int tig = lane & 3;
    const float scale = 0.17677669529663689f;

    __shared__ float sQK[2 * 64 * QS];     // sQ | sK ; reused as sP[64][PS]
    __shared__ float sV[64][QS];
    __shared__ float sBias[169];
    __shared__ float sMask[NTOK * MSK];

    float* sQ = sQK;
    float* sK = sQK + 64 * QS;
    float* sP = sQK;

    for (int idx = tid; idx < 64 * DHEAD; idx += 128) {
        int n = idx >> 5;
        int d = idx & 31;
        float q = 0.f, k = 0.f, v = 0.f;
        if (n < NTOK) {
            const float* base = qkv + (size_t)(b * NTOK + n) * QKVN + h * DHEAD + d;
            q = base[0] * scale;
            k = base[CDIM];
            v = base[2 * CDIM];
        }
        sQ[n * QS + d] = roundtf(q);
        sK[n * QS + d] = roundtf(k);
        sV[n][d] = roundtf(v);
    }
    for (int i = tid; i < 169; i += 128) sBias[i] = bias_table[i * NHEAD + h];
    {
        const float* mrow = mask + (size_t)(b & (NW - 1)) * NTOK * NTOK;
        for (int i = tid; i < NTOK * NTOK; i += 128) {
            int r = i / NTOK;
            int c = i - r * NTOK;
            sMask[r * MSK + c] = mrow[i];
        }
    }
    __syncthreads();

    const int r0 = wid * 16;

    float sacc[8][4];
#pragma unroll
    for (int nt = 0; nt < 8; nt++)
#pragma unroll
        for (int c = 0; c < 4; c++) sacc[nt][c] = 0.f;

#pragma unroll
    for (int ks = 0; ks < 4; ks++) {
        const int k0 = ks * 8;
        uint32_t a[4];
        a[0] = fbits(sQ[(r0 + g    ) * QS + k0 + tig    ]);
        a[1] = fbits(sQ[(r0 + g + 8) * QS + k0 + tig    ]);
        a[2] = fbits(sQ[(r0 + g    ) * QS + k0 + tig + 4]);
        a[3] = fbits(sQ[(r0 + g + 8) * QS + k0 + tig + 4]);
#pragma unroll
        for (int nt = 0; nt < 8; nt++) {
            uint32_t bb[2];
            bb[0] = fbits(sK[(nt * 8 + g) * QS + k0 + tig    ]);
            bb[1] = fbits(sK[(nt * 8 + g) * QS + k0 + tig + 4]);
            mma_tf32(sacc[nt], a, bb);
        }
    }
    __syncthreads();   // all warps done reading sQ/sK before sP (alias) writes

    const int iA = r0 + g;
    const int iB = r0 + g + 8;
    const int yA = iA / 7, xA = iA - yA * 7;
    const int yB = iB / 7, xB = iB - yB * 7;
#pragma unroll
    for (int nt = 0; nt < 8; nt++) {
        const int j0 = nt * 8 + tig * 2;
#pragma unroll
        for (int u = 0; u < 2; u++) {
            int j = j0 + u;
            if (j < NTOK) {
                int yj = j / 7, xj = j - yj * 7;
                if (iA < NTOK) {
                    int rel = (yA - yj + 6) * 13 + (xA - xj + 6);
                    sacc[nt][u] += sBias[rel] + sMask[iA * MSK + j];
                } else sacc[nt][u] = -1e30f;
                if (iB < NTOK) {
                    int rel = (yB - yj + 6) * 13 + (xB - xj + 6);
                    sacc[nt][u + 2] += sBias[rel] + sMask[iB * MSK + j];
                } else sacc[nt][u + 2] = -1e30f;
            } else {
                sacc[nt][u]     = -1e30f;
                sacc[nt][u + 2] = -1e30f;
            }
        }
    }

    float mA = -1e30f, mB = -1e30f;
#pragma unroll
    for (int nt = 0; nt < 8; nt++) {
        mA = fmaxf(mA, fmaxf(sacc[nt][0], sacc[nt][1]));
        mB = fmaxf(mB, fmaxf(sacc[nt][2], sacc[nt][3]));
    }
    mA = fmaxf(mA, __shfl_xor_sync(0xffffffff, mA, 1));
    mA = fmaxf(mA, __shfl_xor_sync(0xffffffff, mA, 2));
    mB = fmaxf(mB, __shfl_xor_sync(0xffffffff, mB, 1));
    mB = fmaxf(mB, __shfl_xor_sync(0xffffffff, mB, 2));

    float sumA = 0.f, sumB = 0.f;
#pragma unroll
    for (int nt = 0; nt < 8; nt++) {
        sacc[nt][0] = __expf(sacc[nt][0] - mA);
        sacc[nt][1] = __expf(sacc[nt][1] - mA);
        sacc[nt][2] = __expf(sacc[nt][2] - mB);
        sacc[nt][3] = __expf(sacc[nt][3] - mB);
        sumA += sacc[nt][0] + sacc[nt][1];
        sumB += sacc[nt][2] + sacc[nt][3];
    }
    sumA += __shfl_xor_sync(0xffffffff, sumA, 1);
    sumA += __shfl_xor_sync(0xffffffff, sumA, 2);
    sumB += __shfl_xor_sync(0xffffffff, sumB, 1);
    sumB += __shfl_xor_sync(0xffffffff, sumB, 2);
    const float invA = 1.0f / sumA;
    const float invB = 1.0f / sumB;

#pragma unroll
    for (int nt = 0; nt < 8; nt++) {
        const int j0 = nt * 8 + tig * 2;
        *(float2*)&sP[iA * PS + j0] =
            make_float2(roundtf(sacc[nt][0] * invA), roundtf(sacc[nt][1] * invA));
        *(float2*)&sP[iB * PS + j0] =
            make_float2(roundtf(sacc[nt][2] * invB), roundtf(sacc[nt][3] * invB));
    }
    __syncwarp();

    float oacc[4][4];
#pragma unroll
    for (int nt = 0; nt < 4; nt++)
#pragma unroll
        for (int c = 0; c < 4; c++) oacc[nt][c] = 0.f;

#pragma unroll
    for (int ks = 0; ks < 8; ks++) {
        const int k0 = ks * 8;
        uint32_t a[4];
        a[0] = fbits(sP[(r0 + g    ) * PS + k0 + tig    ]);
        a[1] = fbits(sP[(r0 + g + 8) * PS + k0 + tig    ]);
        a[2] = fbits(sP[(r0 + g    ) * PS + k0 + tig + 4]);
        a[3] = fbits(sP[(r0 + g + 8) * PS + k0 + tig + 4]);
#pragma unroll
        for (int nt = 0; nt < 4; nt++) {
            uint32_t bb[2];
            bb[0] = fbits(sV[k0 + tig    ][nt * 8 + g]);
            bb[1] = fbits(sV[k0 + tig + 4][nt * 8 + g]);
            mma_tf32(oacc[nt], a, bb);
        }
    }

#pragma unroll
    for (int nt = 0; nt < 4; nt++) {
        const int d0 = nt * 8 + tig * 2;
        if (iA < NTOK)
            *(float2*)(out + (size_t)(b * NTOK + iA) * CDIM + h * DHEAD + d0) =
                make_float2(oacc[nt][0], oacc[nt][1]);
        if (iB < NTOK)
            *(float2*)(out + (size_t)(b * NTOK + iB) * CDIM + h * DHEAD + d0) =
                make_float2(oacc[nt][2], oacc[nt][3]);
    }
}

// ---------------------------------------------------------------------------
// Launch
// ---------------------------------------------------------------------------
extern "C" void kernel_launch(void* const* d_in, const int* in_sizes, int n_in,
                              void* d_out, int out_size)
{
    const float* x          = (const float*)d_in[0];
    const float* mask       = (const float*)d_in[1];
    const float* qkv_w      = (const float*)d_in[2];
    const float* qkv_b      = (const float*)d_in[3];
    const float* proj_w     = (const float*)d_in[4];
    const float* proj_b     = (const float*)d_in[5];
    const float* bias_table = (const float*)d_in[6];
    float* out = (float*)d_out;

    float* qkv;  cudaGetSymbolAddress((void**)&qkv, g_qkv);
    float* att;  cudaGetSymbolAddress((void**)&att, g_att);

    // 1) QKV projection
    {
        dim3 grid(QKVN / GBN, MROWS / GBM);   // (9, 784)
        gemm_tf32_cw<<<grid, 256>>>(x, qkv_w, qkv_b, qkv, MROWS, QKVN, CDIM);
    }

    // 2) Tensor-core windowed attention
    {
        dim3 grid(B_WIN, NHEAD);
        attn_mma<<<grid, 128>>>(qkv, mask, bias_table, att);
    }

    // 3) Output projection
    {
        dim3 grid(CDIM / GBN, MROWS / GBM);   // (3, 784)
        gemm_tf32_cw<<<grid, 256>>>(att, proj_w, proj_b, out, MROWS, CDIM, CDIM);
    }
}

// round 17
// speedup vs baseline: 2.1449x; 1.1711x over previous
#include <cuda_runtime.h>
#include <cstdint>

// ---------------------------------------------------------------------------
// Problem constants
// ---------------------------------------------------------------------------
static constexpr int B_WIN  = 2048;
static constexpr int NTOK   = 49;
static constexpr int CDIM   = 384;
static constexpr int NHEAD  = 12;
static constexpr int DHEAD  = 32;
static constexpr int NW     = 64;
static constexpr int MROWS  = B_WIN * NTOK;   // 100352
static constexpr int QKVN   = 3 * CDIM;       // 1152

// Scratch (no cudaMalloc allowed)
__device__ float g_qkv[(size_t)MROWS * QKVN];
__device__ float g_att[(size_t)MROWS * CDIM];

// ---------------------------------------------------------------------------
// Helpers
// ---------------------------------------------------------------------------
__device__ __forceinline__ void cp_async16(void* smem_dst, const void* gmem_src) {
    uint32_t s = (uint32_t)__cvta_generic_to_shared(smem_dst);
    asm volatile("cp.async.cg.shared.global [%0], [%1], 16;\n" :: "r"(s), "l"(gmem_src));
}
__device__ __forceinline__ void cp_commit() { asm volatile("cp.async.commit_group;\n"); }
template<int N> __device__ __forceinline__ void cp_wait() {
    asm volatile("cp.async.wait_group %0;\n" :: "n"(N));
}
__device__ __forceinline__ uint32_t f2tf32(float x) {
    uint32_t r;
    asm("cvt.rna.tf32.f32 %0, %1;\n" : "=r"(r) : "f"(x));
    return r;
}
__device__ __forceinline__ float roundtf(float x) { return __uint_as_float(f2tf32(x)); }
__device__ __forceinline__ uint32_t fbits(float x) { return __float_as_uint(x); }
__device__ __forceinline__ void mma_tf32(float* c, const uint32_t* a, const uint32_t* b) {
    asm volatile(
        "mma.sync.aligned.m16n8k8.row.col.f32.tf32.tf32.f32 "
        "{%0,%1,%2,%3}, {%4,%5,%6,%7}, {%8,%9}, {%0,%1,%2,%3};\n"
        : "+f"(c[0]), "+f"(c[1]), "+f"(c[2]), "+f"(c[3])
        : "r"(a[0]), "r"(a[1]), "r"(a[2]), "r"(a[3]), "r"(b[0]), "r"(b[1]));
}

// ---------------------------------------------------------------------------
// TF32 GEMM (R7-proven):  C[M,N] = A[M,K] @ B[N,K]^T + bias[N]
// 128x128x16 tiles, 8 warps (64x32 warp tile), 3-stage cp.async, 2 CTAs/SM.
// ---------------------------------------------------------------------------
#define GBM 128
#define GBN 128
#define GBK 16
#define ROWSTRIDE 20
#define A_FLOATS (GBM * ROWSTRIDE)
#define B_FLOATS (GBN * ROWSTRIDE)
#define BUF_FLOATS (A_FLOATS + B_FLOATS)
#define NSTAGE 3
#define SMEM_BYTES (NSTAGE * BUF_FLOATS * 4)   // 61440

__global__ __launch_bounds__(256, 2)
void gemm_tf32_tn_bias(const float* __restrict__ A,
                       const float* __restrict__ B,
                       const float* __restrict__ bias,
                       float* __restrict__ C,
                       int M, int N, int K)
{
    extern __shared__ float smem[];

    const int tid  = threadIdx.x;
    const int wid  = tid >> 5;
    const int lane = tid & 31;
    const int g    = lane >> 2;
    const int tig  = lane & 3;

    const int m0 = blockIdx.y * GBM;
    const int n0 = blockIdx.x * GBN;
    const int warp_m = wid >> 2;
    const int warp_n = wid & 3;

    const int KT = K / GBK;

    float acc[4][4][4];
#pragma unroll
    for (int mt = 0; mt < 4; mt++)
#pragma unroll
        for (int nt = 0; nt < 4; nt++)
#pragma unroll
            for (int r = 0; r < 4; r++) acc[mt][nt][r] = 0.0f;

    auto load_tile = [&](int kt, int buf) {
        float* As = smem + buf * BUF_FLOATS;
        float* Bs = As + A_FLOATS;
        const int k0 = kt * GBK;
#pragma unroll
        for (int j = 0; j < 2; j++) {
            int idx = j * 256 + tid;
            int row = idx >> 2;
            int c4  = (idx & 3) << 2;
            cp_async16(As + row * ROWSTRIDE + c4,
                       A + (size_t)(m0 + row) * K + k0 + c4);
        }
#pragma unroll
        for (int j = 0; j < 2; j++) {
            int idx = j * 256 + tid;
            int row = idx >> 2;
            int c4  = (idx & 3) << 2;
            cp_async16(Bs + row * ROWSTRIDE + c4,
                       B + (size_t)(n0 + row) * K + k0 + c4);
        }
    };

    load_tile(0, 0); cp_commit();
    load_tile(1, 1); cp_commit();

    for (int kt = 0; kt < KT; kt++) {
        if (kt + 2 < KT) load_tile(kt + 2, (kt + 2) % NSTAGE);
        cp_commit();
        cp_wait<2>();
        __syncthreads();

        const float* As = smem + (kt % NSTAGE) * BUF_FLOATS;
        const float* Bs = As + A_FLOATS;

#pragma unroll
        for (int ks = 0; ks < 2; ks++) {
            const int k0 = ks * 8;
            uint32_t af[4][4];
            uint32_t bf[4][2];
#pragma unroll
            for (int mt = 0; mt < 4; mt++) {
                int r = warp_m * 64 + mt * 16 + g;
                af[mt][0] = f2tf32(As[(r    ) * ROWSTRIDE + k0 + tig    ]);
                af[mt][1] = f2tf32(As[(r + 8) * ROWSTRIDE + k0 + tig    ]);
                af[mt][2] = f2tf32(As[(r    ) * ROWSTRIDE + k0 + tig + 4]);
                af[mt][3] = f2tf32(As[(r + 8) * ROWSTRIDE + k0 + tig + 4]);
            }
#pragma unroll
            for (int nt = 0; nt < 4; nt++) {
                int n = warp_n * 32 + nt * 8 + g;
                bf[nt][0] = f2tf32(Bs[n * ROWSTRIDE + k0 + tig    ]);
                bf[nt][1] = f2tf32(Bs[n * ROWSTRIDE + k0 + tig + 4]);
            }
#pragma unroll
            for (int mt = 0; mt < 4; mt++)
#pragma unroll
                for (int nt = 0; nt < 4; nt++)
                    mma_tf32(acc[mt][nt], af[mt], bf[nt]);
        }
        __syncthreads();
    }

#pragma unroll
    for (int mt = 0; mt < 4; mt++) {
        int r0 = m0 + warp_m * 64 + mt * 16 + g;
#pragma unroll
        for (int nt = 0; nt < 4; nt++) {
            int c = n0 + warp_n * 32 + nt * 8 + tig * 2;
            float b0 = bias[c];
            float b1 = bias[c + 1];
            float2 v0 = make_float2(acc[mt][nt][0] + b0, acc[mt][nt][1] + b1);
            float2 v1 = make_float2(acc[mt][nt][2] + b0, acc[mt][nt][3] + b1);
            *(float2*)(C + (size_t)r0 * N + c)       = v0;
            *(float2*)(C + (size_t)(r0 + 8) * N + c) = v1;
        }
    }
}

// ---------------------------------------------------------------------------
// Tensor-core window attention, TWO heads per CTA (256 thr, 8 warps):
// warps 0-3 -> head 2*by, warps 4-7 -> head 2*by+1. Mask staged once,
// shared by both heads. Per-head math identical to the R10-measured kernel.
// Dynamic smem layout (floats):
//   [0, 9216)        sQK[2 groups][4608]   (Q|K per group; sP[64][68] aliases)
//   [9216, 13824)    sV[2 groups][2304]
//   [13824, 14168)   sBias[2 groups][172]
//   [14168, 16872)   sMask[49*52]
// ---------------------------------------------------------------------------
#define QS 36
#define PS 68
#define MSK 52
static constexpr int ATT_SMEM_FLOATS = 16872;
static constexpr int ATT_SMEM_BYTES  = ATT_SMEM_FLOATS * 4;   // 67488

__global__ __launch_bounds__(256)
void attn_mma(const float* __restrict__ qkv,
              const float* __restrict__ mask,
              const float* __restrict__ bias_table,
              float* __restrict__ out)
{
    extern __shared__ float dsm[];

    const int b   = blockIdx.x;
    const int tid = threadIdx.x;
    const int wg  = tid >> 7;             // head group 0/1
    const int t7  = tid & 127;            // thread within group
    const int wi  = (tid >> 5) & 3;       // warp within group
    const int lane = tid & 31;
    const int g   = lane >> 2;
    const int tig = lane & 3;
    const int h   = blockIdx.y * 2 + wg;
    const float scale = 0.17677669529663689f;

    float* sQ    = dsm + wg * 4608;
    float* sK    = sQ + 2304;
    float* sP    = sQ;                    // alias: 64*68 = 4352 <= 4608
    float* sV    = dsm + 9216 + wg * 2304;
    float* sBias = dsm + 13824 + wg * 172;
    float* sMask = dsm + 14168;

    // ---- load Q (scaled+rounded), K, V (rounded); pad rows zero ----
    for (int idx = t7; idx < 64 * DHEAD; idx += 128) {
        int n = idx >> 5;
        int d = idx & 31;
        float q = 0.f, k = 0.f, v = 0.f;
        if (n < NTOK) {
            const float* base = qkv + (size_t)(b * NTOK + n) * QKVN + h * DHEAD + d;
            q = base[0] * scale;
            k = base[CDIM];
            v = base[2 * CDIM];
        }
        sQ[n * QS + d] = roundtf(q);
        sK[n * QS + d] = roundtf(k);
        sV[n * QS + d] = roundtf(v);
    }
    for (int i = t7; i < 169; i += 128) sBias[i] = bias_table[i * NHEAD + h];
    {
        const float* mrow = mask + (size_t)(b & (NW - 1)) * NTOK * NTOK;
        for (int i = tid; i < NTOK * NTOK; i += 256) {
            int r = i / NTOK;
            int c = i - r * NTOK;
            sMask[r * MSK + c] = mrow[i];
        }
    }
    __syncthreads();

    const int r0 = wi * 16;

    // ---- S = Q K^T  (64x64x32) ----
    float sacc[8][4];
#pragma unroll
    for (int nt = 0; nt < 8; nt++)
#pragma unroll
        for (int c = 0; c < 4; c++) sacc[nt][c] = 0.f;

#pragma unroll
    for (int ks = 0; ks < 4; ks++) {
        const int k0 = ks * 8;
        uint32_t a[4];
        a[0] = fbits(sQ[(r0 + g    ) * QS + k0 + tig    ]);
        a[1] = fbits(sQ[(r0 + g + 8) * QS + k0 + tig    ]);
        a[2] = fbits(sQ[(r0 + g    ) * QS + k0 + tig + 4]);
        a[3] = fbits(sQ[(r0 + g + 8) * QS + k0 + tig + 4]);
#pragma unroll
        for (int nt = 0; nt < 8; nt++) {
            uint32_t bb[2];
            bb[0] = fbits(sK[(nt * 8 + g) * QS + k0 + tig    ]);
            bb[1] = fbits(sK[(nt * 8 + g) * QS + k0 + tig + 4]);
            mma_tf32(sacc[nt], a, bb);
        }
    }
    __syncthreads();   // both groups done reading sQ/sK before sP (alias) writes

    // ---- add rel-pos bias + staged mask; kill padding ----
    const int iA = r0 + g;
    const int iB = r0 + g + 8;
    const int yA = iA / 7, xA = iA - yA * 7;
    const int yB = iB / 7, xB = iB - yB * 7;
#pragma unroll
    for (int nt = 0; nt < 8; nt++) {
        const int j0 = nt * 8 + tig * 2;
#pragma unroll
        for (int u = 0; u < 2; u++) {
            int j = j0 + u;
            if (j < NTOK) {
                int yj = j / 7, xj = j - yj * 7;
                if (iA < NTOK) {
                    int rel = (yA - yj + 6) * 13 + (xA - xj + 6);
                    sacc[nt][u] += sBias[rel] + sMask[iA * MSK + j];
                } else sacc[nt][u] = -1e30f;
                if (iB < NTOK) {
                    int rel = (yB - yj + 6) * 13 + (xB - xj + 6);
                    sacc[nt][u + 2] += sBias[rel] + sMask[iB * MSK + j];
                } else sacc[nt][u + 2] = -1e30f;
            } else {
                sacc[nt][u]     = -1e30f;
                sacc[nt][u + 2] = -1e30f;
            }
        }
    }

    // ---- softmax (rows iA, iB across lanes tig 0..3) ----
    float mA = -1e30f, mB = -1e30f;
#pragma unroll
    for (int nt = 0; nt < 8; nt++) {
        mA = fmaxf(mA, fmaxf(sacc[nt][0], sacc[nt][1]));
        mB = fmaxf(mB, fmaxf(sacc[nt][2], sacc[nt][3]));
    }
    mA = fmaxf(mA, __shfl_xor_sync(0xffffffff, mA, 1));
    mA = fmaxf(mA, __shfl_xor_sync(0xffffffff, mA, 2));
    mB = fmaxf(mB, __shfl_xor_sync(0xffffffff, mB, 1));
    mB = fmaxf(mB, __shfl_xor_sync(0xffffffff, mB, 2));

    float sumA = 0.f, sumB = 0.f;
#pragma unroll
    for (int nt = 0; nt < 8; nt++) {
        sacc[nt][0] = __expf(sacc[nt][0] - mA);
        sacc[nt][1] = __expf(sacc[nt][1] - mA);
        sacc[nt][2] = __expf(sacc[nt][2] - mB);
        sacc[nt][3] = __expf(sacc[nt][3] - mB);
        sumA += sacc[nt][0] + sacc[nt][1];
        sumB += sacc[nt][2] + sacc[nt][3];
    }
    sumA += __shfl_xor_sync(0xffffffff, sumA, 1);
    sumA += __shfl_xor_sync(0xffffffff, sumA, 2);
    sumB += __shfl_xor_sync(0xffffffff, sumB, 1);
    sumB += __shfl_xor_sync(0xffffffff, sumB, 2);
    const float invA = 1.0f / sumA;
    const float invB = 1.0f / sumB;

    // ---- P (tf32-rounded) into this warp's 16 rows ----
#pragma unroll
    for (int nt = 0; nt < 8; nt++) {
        const int j0 = nt * 8 + tig * 2;
        *(float2*)&sP[iA * PS + j0] =
            make_float2(roundtf(sacc[nt][0] * invA), roundtf(sacc[nt][1] * invA));
        *(float2*)&sP[iB * PS + j0] =
            make_float2(roundtf(sacc[nt][2] * invB), roundtf(sacc[nt][3] * invB));
    }
    __syncwarp();   // warp reads back only its own rows

    // ---- O = P V  (64x32x64) ----
    float oacc[4][4];
#pragma unroll
    for (int nt = 0; nt < 4; nt++)
#pragma unroll
        for (int c = 0; c < 4; c++) oacc[nt][c] = 0.f;

#pragma unroll
    for (int ks = 0; ks < 8; ks++) {
        const int k0 = ks * 8;
        uint32_t a[4];
        a[0] = fbits(sP[(r0 + g    ) * PS + k0 + tig    ]);
        a[1] = fbits(sP[(r0 + g + 8) * PS + k0 + tig    ]);
        a[2] = fbits(sP[(r0 + g    ) * PS + k0 + tig + 4]);
        a[3] = fbits(sP[(r0 + g + 8) * PS + k0 + tig + 4]);
#pragma unroll
        for (int nt = 0; nt < 4; nt++) {
            uint32_t bb[2];
            bb[0] = fbits(sV[(k0 + tig    ) * QS + nt * 8 + g]);
            bb[1] = fbits(sV[(k0 + tig + 4) * QS + nt * 8 + g]);
            mma_tf32(oacc[nt], a, bb);
        }
    }

    // ---- write O rows < 49 ----
#pragma unroll
    for (int nt = 0; nt < 4; nt++) {
        const int d0 = nt * 8 + tig * 2;
        if (iA < NTOK)
            *(float2*)(out + (size_t)(b * NTOK + iA) * CDIM + h * DHEAD + d0) =
                make_float2(oacc[nt][0], oacc[nt][1]);
        if (iB < NTOK)
            *(float2*)(out + (size_t)(b * NTOK + iB) * CDIM + h * DHEAD + d0) =
                make_float2(oacc[nt][2], oacc[nt][3]);
    }
}

// ---------------------------------------------------------------------------
// Launch
// ---------------------------------------------------------------------------
extern "C" void kernel_launch(void* const* d_in, const int* in_sizes, int n_in,
                              void* d_out, int out_size)
{
    const float* x          = (const float*)d_in[0];
    const float* mask       = (const float*)d_in[1];
    const float* qkv_w      = (const float*)d_in[2];
    const float* qkv_b      = (const float*)d_in[3];
    const float* proj_w     = (const float*)d_in[4];
    const float* proj_b     = (const float*)d_in[5];
    const float* bias_table = (const float*)d_in[6];
    float* out = (float*)d_out;

    float* qkv;  cudaGetSymbolAddress((void**)&qkv, g_qkv);
    float* att;  cudaGetSymbolAddress((void**)&att, g_att);

    static bool attr_set = false;
    if (!attr_set) {
        cudaFuncSetAttribute(gemm_tf32_tn_bias,
                             cudaFuncAttributeMaxDynamicSharedMemorySize, SMEM_BYTES);
        cudaFuncSetAttribute(attn_mma,
                             cudaFuncAttributeMaxDynamicSharedMemorySize, ATT_SMEM_BYTES);
        attr_set = true;
    }

    // 1) QKV projection
    {
        dim3 grid(QKVN / GBN, MROWS / GBM);   // (9, 784)
        gemm_tf32_tn_bias<<<grid, 256, SMEM_BYTES>>>(x, qkv_w, qkv_b, qkv,
                                                     MROWS, QKVN, CDIM);
    }

    // 2) Tensor-core windowed attention (2 heads per CTA)
    {
        dim3 grid(B_WIN, NHEAD / 2);          // (2048, 6)
        attn_mma<<<grid, 256, ATT_SMEM_BYTES>>>(qkv, mask, bias_table, att);
    }

    // 3) Output projection
    {
        dim3 grid(CDIM / GBN, MROWS / GBM);   // (3, 784)
        gemm_tf32_tn_bias<<<grid, 256, SMEM_BYTES>>>(att, proj_w, proj_b, out,
                                                     MROWS, CDIM, CDIM);
    }
}